// round 12
// baseline (speedup 1.0000x reference)
#include <cuda_runtime.h>
#include <math.h>

#define NN 50000
#define NE 400000
#define NG 64
#define DIN 200
#define DH 32
#define NBLK 196    // ceil(NN/256)
#define EBLK2 782   // ceil(NE/512)  (hist: 256 thr x 2 edges)
#define GBLK 391    // ceil(NN/128)  (GEMM blocks: 128 thr, 128 nodes, 64 cols)
#define SCB 1563    // ceil(NE/256)  (scatter blocks: 128 thr x 2 edges)
#define FBLK 6250   // ceil(NN/8)    (flayer/pool blocks: 8 warps, warp per node)

typedef unsigned long long ull;

// ---------------- scratch (device globals — no allocation allowed) ----------
// NOTE: never pass these as kernel args from host code (host shadow symbol +
// ATS silently reads zeros). Select ping-pong buffers with an int in device code.
// Zero-init invariant: g_cnt / g_total / g_sums are zero at every kernel_launch
// entry — BSS zero covers call 1; tail resets (pool: g_cnt, head: sums/total)
// cover graph replays. NO __threadfence anywhere (gpu-scope fence = CCTL.IVALL
// = L1D flush per block — measured +80us regression in round 11).
__device__ __align__(16) float g_tr_a[NN * DH];
__device__ __align__(16) float g_tr_b[NN * DH];
__device__ __align__(16) float g_root_a[NN * DH];
__device__ __align__(16) float g_root_b[NN * DH];
__device__ float g_sums[NG * DH];

__device__ int g_flag_ei;    // nonzero -> edge_index is int32 (k_hist blk 0)
__device__ int g_flag_b;     // nonzero -> batch is int32 (k_scan_bounds blk 0)

__device__ int g_cnt[NN];
__device__ int g_off[NN];
__device__ int g_cur[NN];
__device__ int g_total;
__device__ int g_esrc[NE];
__device__ int g_gstart[NG + 1];

__device__ __forceinline__ float elu1(float v) { return v > 0.f ? v : expm1f(v); }

#define FMA_X2(acc, a, b) \
    asm("fma.rn.f32x2 %0, %1, %2, %0;" : "+l"(acc) : "l"(a), "l"(b))
#define DUP_X2(out, x) \
    asm("mov.b64 %0, {%1, %1};" : "=l"(out) : "r"(__float_as_uint(x)))
#define UNPK_X2(lo, hi, in) \
    asm("mov.b64 {%0, %1}, %2;" : "=f"(lo), "=f"(hi) : "l"(in))
#define PACK_X2(out, lo, hi) \
    asm("mov.b64 %0, {%1, %2};" : "=l"(out) : "f"(lo), "f"(hi))

// ---------------------------------------------------------------------------
// dtype decode helpers (clamped)
// ---------------------------------------------------------------------------
__device__ __forceinline__ int edge_at(const void* ei_raw, int idx, int is32)
{
    int v = is32 ? ((const int*)ei_raw)[idx] : (int)((const long long*)ei_raw)[idx];
    v &= 0x7fffffff;
    return (v < NN) ? v : 0;
}

__device__ __forceinline__ int batch_at(const void* b_raw, int i, int is32)
{
    int g = is32 ? ((const int*)b_raw)[i] : (int)((const long long*)b_raw)[i];
    g &= 0x7fffffff;
    return (g < NG) ? g : (NG - 1);
}

// 32-sample dtype probe by warp 0: int64 values < 2^31 have all-zero odd
// 32-bit words; int32 payloads essentially never do. Each block computes its
// own flag (no cross-block ordering needed).
__device__ __forceinline__ int probe32(const unsigned* w, int stride_pairs)
{
    const int lane = threadIdx.x & 31;
    const unsigned v = w[2 * (lane * stride_pairs) + 1];
    return __ballot_sync(0xffffffffu, v != 0) != 0;
}

// ---------------------------------------------------------------------------
// Kernel 1: dst histogram + edge dtype detection (warp-0 probe, shared flag).
// g_cnt pre-zeroed by the zero-invariant.
// ---------------------------------------------------------------------------
__global__ void k_hist(const unsigned* __restrict__ ei_w)
{
    __shared__ int s_flag;
    const int tid = threadIdx.x;
    if (tid < 32) {
        const int f = probe32(ei_w, 12497);          // samples spread over 800k words
        if (tid == 0) {
            s_flag = f;
            if (blockIdx.x == 0) g_flag_ei = f;
        }
    }
    __syncthreads();
    const int is32 = s_flag;

    const int base = blockIdx.x * 256 + tid;
#pragma unroll
    for (int q = 0; q < 2; q++) {
        const int e = base + q * (EBLK2 * 256);
        if (e < NE) atomicAdd(&g_cnt[edge_at(ei_w, NE + e, is32)], 1);
    }
}

// ---------------------------------------------------------------------------
// Kernel 2: single-pass scan (block scan + atomic base; bases need not be
// monotone since consumers use beg + cnt) fused with graph-boundary build.
// Batch dtype probe samples the sorted tail (values ~ NG-1, nonzero).
// ---------------------------------------------------------------------------
__global__ void k_scan_bounds(const void* __restrict__ b_raw)
{
    __shared__ int s[256];
    __shared__ int base_sh;
    __shared__ int s_flag;
    const int tid = threadIdx.x;
    if (tid < 32) {
        const unsigned* bw = (const unsigned*)b_raw;
        const int lane = tid;
        const unsigned v = bw[2 * (24900 + lane) + 1];  // tail indices 24900..24931
        const int f = __ballot_sync(0xffffffffu, v != 0) != 0;
        if (tid == 0) {
            s_flag = f;
            if (blockIdx.x == 0) g_flag_b = f;
        }
    }
    __syncthreads();
    const int is32 = s_flag;

    const int i = blockIdx.x * 256 + tid;
    const int v = (i < NN) ? g_cnt[i] : 0;
    s[tid] = v;
    __syncthreads();
#pragma unroll
    for (int d = 1; d < 256; d <<= 1) {
        const int t = (tid >= d) ? s[tid - d] : 0;
        __syncthreads();
        s[tid] += t;
        __syncthreads();
    }
    if (tid == 255) base_sh = atomicAdd(&g_total, s[255]);
    __syncthreads();
    if (i < NN) {
        const int o = base_sh + s[tid] - v;
        g_off[i] = o;
        g_cur[i] = o;
    }

    if (i < NN) {
        const int g  = batch_at(b_raw, i, is32);
        const int gp = (i == 0) ? -1 : batch_at(b_raw, i - 1, is32);
        for (int q = gp + 1; q <= g; q++) g_gstart[q] = i;
        if (i == NN - 1)
            for (int q = g + 1; q <= NG; q++) g_gstart[q] = NN;
    }
}

// ---------------------------------------------------------------------------
// Kernel 3 (fused): blocks [0,GBLK) = GEMM1; blocks [GBLK,GBLK+SCB) = CSR
// scatter. GEMM1: [50000,200] @ [W1r|W1l][200,64], node-pair f32x2 packing
// (acc pair = adjacent nodes, W pre-duplicated in smem during staging ->
// zero dups in inner loop). Evidence round 11: displaced from top launch.
// ---------------------------------------------------------------------------
__global__ __launch_bounds__(128) void k_gemm1_scatter(const float* __restrict__ x,
                                                       const float* __restrict__ Wr,
                                                       const float* __restrict__ Wl,
                                                       const float* __restrict__ b,
                                                       const void* __restrict__ ei_raw)
{
    if (blockIdx.x >= GBLK) {
        const int base = (blockIdx.x - GBLK) * 256 + threadIdx.x;
        const int is32 = g_flag_ei;
#pragma unroll
        for (int q = 0; q < 2; q++) {
            const int e = base + q * 128;
            if (e < NE) {
                const int d = edge_at(ei_raw, NE + e, is32);
                const int sres = edge_at(ei_raw, e, is32);
                const int pos = atomicAdd(&g_cur[d], 1);
                g_esrc[pos] = sres;
            }
        }
        return;
    }

    __shared__ __align__(16) float Xs[2][8 * 128];   // [buf][k][node]
    __shared__ __align__(16) ull   Wd[2][8 * 64];    // [buf][k*64+c] = (w,w)
    __shared__ float bs[32];

    const int tid = threadIdx.x;
    const int n0  = blockIdx.x * 128;
    if (tid < 32) bs[tid] = b[tid];

    const int cg = tid & 7;        // col group (8 cols)
    const int ng = tid >> 3;       // node group (8 nodes = 4 pairs), 0..15

    ull acc2[4][8];                // [node pair][col]
#pragma unroll
    for (int i = 0; i < 4; i++)
#pragma unroll
        for (int j = 0; j < 8; j++) acc2[i][j] = 0ULL;

    const int  nld = n0 + tid;
    const bool vld = nld < NN;
    const float4* xrow = reinterpret_cast<const float4*>(x + (long)nld * DIN);

    float4 xa, xb;
    float  wv[4];

#define LOAD_TILE(t)                                                          \
    do {                                                                      \
        xa = make_float4(0.f, 0.f, 0.f, 0.f); xb = xa;                        \
        if (vld) { xa = xrow[(t) * 2]; xb = xrow[(t) * 2 + 1]; }              \
        _Pragma("unroll")                                                     \
        for (int j = 0; j < 4; j++) {                                         \
            const int idx = j * 128 + tid;       /* 0..511 = kk*64+c */       \
            const int kk = idx >> 6, c = idx & 63;                            \
            wv[j] = (c < 32) ? Wr[((t) * 8 + kk) * 32 + c]                    \
                             : Wl[((t) * 8 + kk) * 32 + c - 32];              \
        }                                                                     \
    } while (0)

#define STORE_TILE(bf)                                                        \
    do {                                                                      \
        Xs[bf][0 * 128 + tid] = xa.x; Xs[bf][1 * 128 + tid] = xa.y;           \
        Xs[bf][2 * 128 + tid] = xa.z; Xs[bf][3 * 128 + tid] = xa.w;           \
        Xs[bf][4 * 128 + tid] = xb.x; Xs[bf][5 * 128 + tid] = xb.y;           \
        Xs[bf][6 * 128 + tid] = xb.z; Xs[bf][7 * 128 + tid] = xb.w;           \
        _Pragma("unroll")                                                     \
        for (int j = 0; j < 4; j++) {                                         \
            ull wd; DUP_X2(wd, wv[j]);                                        \
            Wd[bf][j * 128 + tid] = wd;                                       \
        }                                                                     \
    } while (0)

    LOAD_TILE(0);
    STORE_TILE(0);
    __syncthreads();

    int buf = 0;
    for (int t = 0; t < 25; t++) {
        if (t < 24) LOAD_TILE(t + 1);                // LDG in flight during compute

#pragma unroll
        for (int kk = 0; kk < 8; kk++) {
            const ull* xp = reinterpret_cast<const ull*>(Xs[buf] + kk * 128 + ng * 8);
            const ull xp0 = xp[0], xp1 = xp[1], xp2 = xp[2], xp3 = xp[3];
            const ull* wp = Wd[buf] + kk * 64 + cg * 8;
#pragma unroll
            for (int j = 0; j < 8; j++) {
                const ull wdj = wp[j];
                FMA_X2(acc2[0][j], xp0, wdj);
                FMA_X2(acc2[1][j], xp1, wdj);
                FMA_X2(acc2[2][j], xp2, wdj);
                FMA_X2(acc2[3][j], xp3, wdj);
            }
        }

        if (t < 24) STORE_TILE(buf ^ 1);             // other buffer: race-free
        __syncthreads();
        buf ^= 1;
    }
#undef LOAD_TILE
#undef STORE_TILE

    const int c0 = cg * 8;
#pragma unroll
    for (int i = 0; i < 4; i++) {
        const int ne = n0 + ng * 8 + 2 * i;          // even node of pair
        float lo[8], hi[8];
#pragma unroll
        for (int j = 0; j < 8; j++) UNPK_X2(lo[j], hi[j], acc2[i][j]);

#pragma unroll
        for (int p = 0; p < 2; p++) {
            const int node = ne + p;
            if (node >= NN) continue;
            const float* c = p ? hi : lo;
            float4 v0 = make_float4(c[0], c[1], c[2], c[3]);
            float4 v1 = make_float4(c[4], c[5], c[6], c[7]);
            if (cg < 4) {
                *reinterpret_cast<float4*>(g_tr_a + node * DH + c0)     = v0;
                *reinterpret_cast<float4*>(g_tr_a + node * DH + c0 + 4) = v1;
            } else {
                const int cc = c0 - 32;
                v0.x += bs[cc + 0]; v0.y += bs[cc + 1]; v0.z += bs[cc + 2]; v0.w += bs[cc + 3];
                v1.x += bs[cc + 4]; v1.y += bs[cc + 5]; v1.z += bs[cc + 6]; v1.w += bs[cc + 7];
                *reinterpret_cast<float4*>(g_root_a + node * DH + cc)     = v0;
                *reinterpret_cast<float4*>(g_root_a + node * DH + cc + 4) = v1;
            }
        }
    }
}

// ---------------------------------------------------------------------------
// Fused layer kernel (layers 1->2, 2->3): warp per node (round-8 proven).
// Buffers picked by sel in device code (sel=0: a->b, sel=1: b->a).
// ---------------------------------------------------------------------------
__global__ __launch_bounds__(256) void k_flayer(int sel,
                                                const float* __restrict__ Wr,
                                                const float* __restrict__ Wl,
                                                const float* __restrict__ b)
{
    __shared__ __align__(16) ull Wp[32 * 32];  // [k][lane]=(Wr,Wl)
    __shared__ float bs[32];
    __shared__ float hs[8][32];

    const int tid = threadIdx.x;
    for (int i = tid; i < 1024; i += 256) {
        const int k = i >> 5, c = i & 31;
        ull p;
        PACK_X2(p, Wr[k * 32 + c], Wl[k * 32 + c]);
        Wp[i] = p;
    }
    if (tid < 32) bs[tid] = b[tid];
    __syncthreads();

    const float* tr_in   = sel ? g_tr_b   : g_tr_a;
    const float* root_in = sel ? g_root_b : g_root_a;
    float* tr_out   = sel ? g_tr_a   : g_tr_b;
    float* root_out = sel ? g_root_a : g_root_b;

    const int w    = tid >> 5;
    const int lane = tid & 31;
    const int node = (blockIdx.x << 3) + w;
    if (node >= NN) return;

    const int beg = g_off[node];
    const int end = beg + g_cnt[node];
    float acc = 0.f;
    int k = beg;
    for (; k + 3 < end; k += 4) {
        const int s0 = g_esrc[k + 0], s1 = g_esrc[k + 1];
        const int s2 = g_esrc[k + 2], s3 = g_esrc[k + 3];
        acc += tr_in[s0 * DH + lane] + tr_in[s1 * DH + lane]
             + tr_in[s2 * DH + lane] + tr_in[s3 * DH + lane];
    }
    for (; k < end; k++) acc += tr_in[g_esrc[k] * DH + lane];

    const float h = elu1(acc + root_in[node * DH + lane]);
    hs[w][lane] = h;
    __syncwarp();

    ull a2 = 0ULL;
#pragma unroll
    for (int kk = 0; kk < 32; kk++) {
        ull hd;
        DUP_X2(hd, hs[w][kk]);                    // LDS broadcast
        FMA_X2(a2, hd, Wp[kk * 32 + lane]);
    }
    float m, r;
    UNPK_X2(m, r, a2);
    tr_out[node * DH + lane]   = m;
    root_out[node * DH + lane] = r + bs[lane];
}

// ---------------------------------------------------------------------------
// Fused layer 3 + pool: h = elu(aggr + root); atomicAdd into per-graph sums.
// NO fences. Tail: reset g_cnt[node] for the next graph replay.
// ---------------------------------------------------------------------------
__global__ __launch_bounds__(256) void k_flayer3_pool(const void* __restrict__ b_raw)
{
    const int tid  = threadIdx.x;
    const int w    = tid >> 5;
    const int lane = tid & 31;
    const int node = (blockIdx.x << 3) + w;
    if (node >= NN) return;
    const int is32b = g_flag_b;

    const int beg = g_off[node];
    const int cnt = g_cnt[node];
    const int end = beg + cnt;
    float acc = 0.f;
    int k = beg;
    for (; k + 3 < end; k += 4) {
        const int s0 = g_esrc[k + 0], s1 = g_esrc[k + 1];
        const int s2 = g_esrc[k + 2], s3 = g_esrc[k + 3];
        acc += g_tr_a[s0 * DH + lane] + g_tr_a[s1 * DH + lane]
             + g_tr_a[s2 * DH + lane] + g_tr_a[s3 * DH + lane];
    }
    for (; k < end; k++) acc += g_tr_a[g_esrc[k] * DH + lane];

    const float h = elu1(acc + g_root_a[node * DH + lane]);
    const int g = batch_at(b_raw, node, is32b);
    atomicAdd(&g_sums[g * DH + lane], h);
    if (lane == 0) g_cnt[node] = 0;               // zero-invariant for next call
}

// ---------------------------------------------------------------------------
// Head: pooled mean -> linear[32,2] -> log_softmax. Also resets g_sums and
// g_total for the next replay (zero-invariant).
// ---------------------------------------------------------------------------
__global__ void k_head(const float* __restrict__ Wlin, const float* __restrict__ blin,
                       float* __restrict__ out)
{
    const int tid = threadIdx.x;
    float l0 = 0.f, l1 = 0.f;
    if (tid < NG) {
        const int cnt = g_gstart[tid + 1] - g_gstart[tid];
        const float inv = 1.f / fmaxf((float)cnt, 1.f);
        l0 = blin[0]; l1 = blin[1];
#pragma unroll
        for (int c = 0; c < DH; c++) {
            const float p = g_sums[tid * DH + c] * inv;
            l0 += p * Wlin[c * 2 + 0];
            l1 += p * Wlin[c * 2 + 1];
        }
    }
    __syncthreads();                               // all reads done before reset
    if (tid < NG) {
        const float m   = fmaxf(l0, l1);
        const float lse = m + logf(expf(l0 - m) + expf(l1 - m));
        out[tid * 2 + 0] = l0 - lse;
        out[tid * 2 + 1] = l1 - lse;
    }
    for (int i = tid; i < NG * DH; i += 256) g_sums[i] = 0.f;
    if (tid == 0) g_total = 0;
}

// ---------------------------------------------------------------------------
extern "C" void kernel_launch(void* const* d_in, const int* in_sizes, int n_in,
                              void* d_out, int out_size)
{
    const void *p_x = 0, *p_ei = 0, *p_batch = 0;
    const void *p_W1[2] = {0, 0};
    const void *p_W23[4] = {0, 0, 0, 0};
    const void *p_b[3] = {0, 0, 0};
    const void *p_Wlin = 0, *p_blin = 0;
    int n64 = 0, n1024 = 0, n32 = 0;
    for (int i = 0; i < n_in; i++) {
        const int s = in_sizes[i];
        if      (s == NN * DIN) p_x = d_in[i];
        else if (s == 2 * NE)   p_ei = d_in[i];
        else if (s == NN)       p_batch = d_in[i];
        else if (s == DIN * DH) { if (n64 < 2) p_W1[n64++] = d_in[i]; }
        else if (s == DH * DH)  { if (n1024 < 4) p_W23[n1024++] = d_in[i]; }
        else if (s == DH)       { if (n32 < 3) p_b[n32++] = d_in[i]; }
        else if (s == DH * 2)   p_Wlin = d_in[i];
        else if (s == 2)        p_blin = d_in[i];
    }
    const float* x    = (const float*)p_x;
    const float* W1r  = (const float*)p_W1[0];
    const float* W1l  = (const float*)p_W1[1];
    const float* b1   = (const float*)p_b[0];
    const float* W2r  = (const float*)p_W23[0];
    const float* W2l  = (const float*)p_W23[1];
    const float* b2   = (const float*)p_b[1];
    const float* W3r  = (const float*)p_W23[2];
    const float* W3l  = (const float*)p_W23[3];
    const float* b3   = (const float*)p_b[2];
    const float* Wlin = (const float*)p_Wlin;
    const float* blin = (const float*)p_blin;
    float* out = (float*)d_out;

    k_hist<<<EBLK2, 256>>>((const unsigned*)p_ei);
    k_scan_bounds<<<NBLK, 256>>>(p_batch);
    k_gemm1_scatter<<<GBLK + SCB, 128>>>(x, W1r, W1l, b1, p_ei);
    k_flayer<<<FBLK, 256>>>(0, W2r, W2l, b2);     // a -> b (L1 act + L2 linear)
    k_flayer<<<FBLK, 256>>>(1, W3r, W3l, b3);     // b -> a (L2 act + L3 linear)
    k_flayer3_pool<<<FBLK, 256>>>(p_batch);       // L3 act + pool
    k_head<<<1, 256>>>(Wlin, blin, out);
}

// round 13
// speedup vs baseline: 1.5484x; 1.5484x over previous
#include <cuda_runtime.h>
#include <math.h>

#define NN 50000
#define NE 400000
#define NG 64
#define DIN 200
#define DH 32
#define NBLK 196    // ceil(NN/256)
#define EBLK 1563   // ceil(NE/256)
#define GBLK 391    // ceil(NN/128)  (GEMM blocks: 128 thr, 128 nodes, 64 cols)
#define SCB2 3125   // ceil(NE/128)  (scatter blocks: 128 thr, 1 edge)

typedef unsigned long long ull;

// ---------------- scratch (device globals — no allocation allowed) ----------
// NOTE: never pass these as kernel args from host code (host shadow symbol +
// ATS silently reads zeros). Select ping-pong buffers with an int in device
// code. ALL scratch is explicitly zeroed at the top of every kernel_launch
// (k_detect_zero) — replays are identical by construction, no state coupling.
// NO __threadfence anywhere (gpu-scope fence = CCTL.IVALL = per-block L1D
// flush; measured disaster in round 11).
__device__ __align__(16) float g_tr_a[NN * DH];
__device__ __align__(16) float g_tr_b[NN * DH];
__device__ __align__(16) float g_root_a[NN * DH];
__device__ __align__(16) float g_root_b[NN * DH];
__device__ float g_sums[NG * DH];

__device__ int g_srci[NE];
__device__ int g_dsti[NE];
__device__ int g_flag_ei;    // nonzero -> edge_index is int32
__device__ int g_flag_b;     // nonzero -> batch is int32

__device__ int g_cnt[NN];
__device__ int g_off[NN];
__device__ int g_cur[NN];
__device__ int g_total;
__device__ int g_esrc[NE];
__device__ int g_gstart[NG + 1];

__device__ __forceinline__ float elu1(float v) { return v > 0.f ? v : expm1f(v); }

#define FMA_X2(acc, a, b) \
    asm("fma.rn.f32x2 %0, %1, %2, %0;" : "+l"(acc) : "l"(a), "l"(b))
#define DUP_X2(out, x) \
    asm("mov.b64 %0, {%1, %1};" : "=l"(out) : "r"(__float_as_uint(x)))
#define UNPK_X2(lo, hi, in) \
    asm("mov.b64 {%0, %1}, %2;" : "=f"(lo), "=f"(hi) : "l"(in))
#define PACK_X2(out, lo, hi) \
    asm("mov.b64 %0, {%1, %2};" : "=l"(out) : "f"(lo), "f"(hi))

// ---------------------------------------------------------------------------
// Kernel 1: zero ALL scratch + dtype detection (block 0 samples odd 32-bit
// words: int64 values < 2^31 have zero high words; int32 payloads don't)
// ---------------------------------------------------------------------------
__global__ void k_detect_zero(const unsigned* __restrict__ ei_w,
                              const unsigned* __restrict__ b_w)
{
    const int i = blockIdx.x * blockDim.x + threadIdx.x;
    if (i < NN) g_cnt[i] = 0;
    if (i < NG * DH) g_sums[i] = 0.f;
    if (i == 0) g_total = 0;

    if (blockIdx.x == 0) {
        __shared__ int s_ei, s_b;
        const int tid = threadIdx.x;
        if (tid == 0) { s_ei = 0; s_b = 0; }
        __syncthreads();
        { const int k = tid * 1562;  if (ei_w[2 * k + 1] != 0) atomicOr(&s_ei, 1); }
        { const int k = 24744 + tid; if (b_w[2 * k + 1] != 0)  atomicOr(&s_b, 1); }
        __syncthreads();
        if (tid == 0) { g_flag_ei = s_ei; g_flag_b = s_b; }
    }
}

// ---------------------------------------------------------------------------
// Kernel 2: decode edges (either dtype) + clamp + dst histogram
// ---------------------------------------------------------------------------
__global__ void k_conv_hist(const void* __restrict__ ei_raw)
{
    const int e = blockIdx.x * blockDim.x + threadIdx.x;
    if (e >= NE) return;
    int s, d;
    if (g_flag_ei) {
        const int* p = (const int*)ei_raw;
        s = p[e]; d = p[NE + e];
    } else {
        const long long* p = (const long long*)ei_raw;
        s = (int)p[e]; d = (int)p[NE + e];
    }
    s &= 0x7fffffff; d &= 0x7fffffff;
    s = (s < NN) ? s : 0;
    d = (d < NN) ? d : 0;
    g_srci[e] = s;
    g_dsti[e] = d;
    atomicAdd(&g_cnt[d], 1);
}

// ---------------------------------------------------------------------------
// Kernel 3: single-pass scan (block scan + atomic base; bases need not be
// monotone since consumers use beg + cnt) fused with graph-boundary build.
// ---------------------------------------------------------------------------
__device__ __forceinline__ int batch_at(const void* b_raw, int i, int is32)
{
    int g = is32 ? ((const int*)b_raw)[i] : (int)((const long long*)b_raw)[i];
    g &= 0x7fffffff;
    return (g < NG) ? g : (NG - 1);
}

__global__ void k_scan_bounds(const void* __restrict__ b_raw)
{
    __shared__ int s[256];
    __shared__ int base_sh;
    const int tid = threadIdx.x;
    const int i = blockIdx.x * 256 + tid;
    const int v = (i < NN) ? g_cnt[i] : 0;
    s[tid] = v;
    __syncthreads();
#pragma unroll
    for (int d = 1; d < 256; d <<= 1) {
        const int t = (tid >= d) ? s[tid - d] : 0;
        __syncthreads();
        s[tid] += t;
        __syncthreads();
    }
    if (tid == 255) base_sh = atomicAdd(&g_total, s[255]);
    __syncthreads();
    if (i < NN) {
        const int o = base_sh + s[tid] - v;
        g_off[i] = o;
        g_cur[i] = o;
    }

    if (i < NN) {
        const int is32 = g_flag_b;
        const int g  = batch_at(b_raw, i, is32);
        const int gp = (i == 0) ? -1 : batch_at(b_raw, i - 1, is32);
        for (int q = gp + 1; q <= g; q++) g_gstart[q] = i;
        if (i == NN - 1)
            for (int q = g + 1; q <= NG; q++) g_gstart[q] = NN;
    }
}

// ---------------------------------------------------------------------------
// Kernel 4 (fused): blocks [0,GBLK) = GEMM1; blocks [GBLK,GBLK+SCB2) = CSR
// scatter (reads pre-decoded g_srci/g_dsti — champion structure).
// GEMM1: [50000,200] @ [W1r|W1l][200,64]. Node-pair f32x2 packing: acc pair =
// (node 2i, node 2i+1); W pre-DUPLICATED into smem during staging -> inner
// loop has zero mov.b64 dups (38 instr/kk vs 46). 128 thr / 128 nodes /
// 64 cols, double-buffered, one __syncthreads per K-tile.
// ---------------------------------------------------------------------------
__global__ __launch_bounds__(128) void k_gemm1_scatter(const float* __restrict__ x,
                                                       const float* __restrict__ Wr,
                                                       const float* __restrict__ Wl,
                                                       const float* __restrict__ b)
{
    if (blockIdx.x >= GBLK) {
        const int e = (blockIdx.x - GBLK) * 128 + threadIdx.x;
        if (e >= NE) return;
        const int pos = atomicAdd(&g_cur[g_dsti[e]], 1);
        g_esrc[pos] = g_srci[e];
        return;
    }

    __shared__ __align__(16) float Xs[2][8 * 128];   // [buf][k][node]
    __shared__ __align__(16) ull   Wd[2][8 * 64];    // [buf][k*64+c] = (w,w)
    __shared__ float bs[32];

    const int tid = threadIdx.x;
    const int n0  = blockIdx.x * 128;
    if (tid < 32) bs[tid] = b[tid];

    const int cg = tid & 7;        // col group (8 cols)
    const int ng = tid >> 3;       // node group (8 nodes = 4 pairs), 0..15

    ull acc2[4][8];                // [node pair][col]
#pragma unroll
    for (int i = 0; i < 4; i++)
#pragma unroll
        for (int j = 0; j < 8; j++) acc2[i][j] = 0ULL;

    const int  nld = n0 + tid;
    const bool vld = nld < NN;
    const float4* xrow = reinterpret_cast<const float4*>(x + (long)nld * DIN);

    float4 xa, xb;
    float  wv[4];

#define LOAD_TILE(t)                                                          \
    do {                                                                      \
        xa = make_float4(0.f, 0.f, 0.f, 0.f); xb = xa;                        \
        if (vld) { xa = xrow[(t) * 2]; xb = xrow[(t) * 2 + 1]; }              \
        _Pragma("unroll")                                                     \
        for (int j = 0; j < 4; j++) {                                         \
            const int idx = j * 128 + tid;       /* 0..511 = kk*64+c */       \
            const int kk = idx >> 6, c = idx & 63;                            \
            wv[j] = (c < 32) ? Wr[((t) * 8 + kk) * 32 + c]                    \
                             : Wl[((t) * 8 + kk) * 32 + c - 32];              \
        }                                                                     \
    } while (0)

#define STORE_TILE(bf)                                                        \
    do {                                                                      \
        Xs[bf][0 * 128 + tid] = xa.x; Xs[bf][1 * 128 + tid] = xa.y;           \
        Xs[bf][2 * 128 + tid] = xa.z; Xs[bf][3 * 128 + tid] = xa.w;           \
        Xs[bf][4 * 128 + tid] = xb.x; Xs[bf][5 * 128 + tid] = xb.y;           \
        Xs[bf][6 * 128 + tid] = xb.z; Xs[bf][7 * 128 + tid] = xb.w;           \
        _Pragma("unroll")                                                     \
        for (int j = 0; j < 4; j++) {                                         \
            ull wd; DUP_X2(wd, wv[j]);                                        \
            Wd[bf][j * 128 + tid] = wd;                                       \
        }                                                                     \
    } while (0)

    LOAD_TILE(0);
    STORE_TILE(0);
    __syncthreads();

    int buf = 0;
    for (int t = 0; t < 25; t++) {
        if (t < 24) LOAD_TILE(t + 1);                // LDG in flight during compute

#pragma unroll
        for (int kk = 0; kk < 8; kk++) {
            const ull* xp = reinterpret_cast<const ull*>(Xs[buf] + kk * 128 + ng * 8);
            const ull xp0 = xp[0], xp1 = xp[1], xp2 = xp[2], xp3 = xp[3];
            const ull* wp = Wd[buf] + kk * 64 + cg * 8;
#pragma unroll
            for (int j = 0; j < 8; j++) {
                const ull wdj = wp[j];
                FMA_X2(acc2[0][j], xp0, wdj);
                FMA_X2(acc2[1][j], xp1, wdj);
                FMA_X2(acc2[2][j], xp2, wdj);
                FMA_X2(acc2[3][j], xp3, wdj);
            }
        }

        if (t < 24) STORE_TILE(buf ^ 1);             // other buffer: race-free
        __syncthreads();
        buf ^= 1;
    }
#undef LOAD_TILE
#undef STORE_TILE

    const int c0 = cg * 8;
#pragma unroll
    for (int i = 0; i < 4; i++) {
        const int ne = n0 + ng * 8 + 2 * i;          // even node of pair
        float lo[8], hi[8];
#pragma unroll
        for (int j = 0; j < 8; j++) UNPK_X2(lo[j], hi[j], acc2[i][j]);

#pragma unroll
        for (int p = 0; p < 2; p++) {
            const int node = ne + p;
            if (node >= NN) continue;
            const float* c = p ? hi : lo;
            float4 v0 = make_float4(c[0], c[1], c[2], c[3]);
            float4 v1 = make_float4(c[4], c[5], c[6], c[7]);
            if (cg < 4) {
                *reinterpret_cast<float4*>(g_tr_a + node * DH + c0)     = v0;
                *reinterpret_cast<float4*>(g_tr_a + node * DH + c0 + 4) = v1;
            } else {
                const int cc = c0 - 32;
                v0.x += bs[cc + 0]; v0.y += bs[cc + 1]; v0.z += bs[cc + 2]; v0.w += bs[cc + 3];
                v1.x += bs[cc + 4]; v1.y += bs[cc + 5]; v1.z += bs[cc + 6]; v1.w += bs[cc + 7];
                *reinterpret_cast<float4*>(g_root_a + node * DH + cc)     = v0;
                *reinterpret_cast<float4*>(g_root_a + node * DH + cc + 4) = v1;
            }
        }
    }
}

// ---------------------------------------------------------------------------
// Fused layer kernel (layers 1->2, 2->3): warp per node (champion version).
// Buffers picked by sel in device code (sel=0: a->b, sel=1: b->a).
// ---------------------------------------------------------------------------
__global__ __launch_bounds__(256) void k_flayer(int sel,
                                                const float* __restrict__ Wr,
                                                const float* __restrict__ Wl,
                                                const float* __restrict__ b)
{
    __shared__ __align__(16) ull Wp[32 * 32];  // [k][lane]=(Wr,Wl)
    __shared__ float bs[32];
    __shared__ float hs[8][32];

    const int tid = threadIdx.x;
    for (int i = tid; i < 1024; i += 256) {
        const int k = i >> 5, c = i & 31;
        ull p;
        PACK_X2(p, Wr[k * 32 + c], Wl[k * 32 + c]);
        Wp[i] = p;
    }
    if (tid < 32) bs[tid] = b[tid];
    __syncthreads();

    const float* tr_in   = sel ? g_tr_b   : g_tr_a;
    const float* root_in = sel ? g_root_b : g_root_a;
    float* tr_out   = sel ? g_tr_a   : g_tr_b;
    float* root_out = sel ? g_root_a : g_root_b;

    const int w    = tid >> 5;
    const int lane = tid & 31;
    const int node = (blockIdx.x << 3) + w;
    if (node >= NN) return;

    const int beg = g_off[node];
    const int end = beg + g_cnt[node];
    float acc = 0.f;
    int k = beg;
    for (; k + 3 < end; k += 4) {
        const int s0 = g_esrc[k + 0], s1 = g_esrc[k + 1];
        const int s2 = g_esrc[k + 2], s3 = g_esrc[k + 3];
        acc += tr_in[s0 * DH + lane] + tr_in[s1 * DH + lane]
             + tr_in[s2 * DH + lane] + tr_in[s3 * DH + lane];
    }
    for (; k < end; k++) acc += tr_in[g_esrc[k] * DH + lane];

    const float h = elu1(acc + root_in[node * DH + lane]);
    hs[w][lane] = h;
    __syncwarp();

    ull a2 = 0ULL;
#pragma unroll
    for (int kk = 0; kk < 32; kk++) {
        ull hd;
        DUP_X2(hd, hs[w][kk]);                    // LDS broadcast
        FMA_X2(a2, hd, Wp[kk * 32 + lane]);
    }
    float m, r;
    UNPK_X2(m, r, a2);
    tr_out[node * DH + lane]   = m;
    root_out[node * DH + lane] = r + bs[lane];
}

// ---------------------------------------------------------------------------
// Fused layer 3 + pool: reads a-buffers; h = elu(aggr + root); atomic pool.
// ---------------------------------------------------------------------------
__global__ __launch_bounds__(256) void k_flayer3_pool(const void* __restrict__ b_raw)
{
    const int tid  = threadIdx.x;
    const int w    = tid >> 5;
    const int lane = tid & 31;
    const int node = (blockIdx.x << 3) + w;
    if (node >= NN) return;

    const int beg = g_off[node];
    const int end = beg + g_cnt[node];
    float acc = 0.f;
    int k = beg;
    for (; k + 3 < end; k += 4) {
        const int s0 = g_esrc[k + 0], s1 = g_esrc[k + 1];
        const int s2 = g_esrc[k + 2], s3 = g_esrc[k + 3];
        acc += g_tr_a[s0 * DH + lane] + g_tr_a[s1 * DH + lane]
             + g_tr_a[s2 * DH + lane] + g_tr_a[s3 * DH + lane];
    }
    for (; k < end; k++) acc += g_tr_a[g_esrc[k] * DH + lane];

    const float h = elu1(acc + g_root_a[node * DH + lane]);
    const int g = batch_at(b_raw, node, g_flag_b);
    atomicAdd(&g_sums[g * DH + lane], h);
}

// ---------------------------------------------------------------------------
// Head: pooled mean -> linear[32,2] -> log_softmax
// ---------------------------------------------------------------------------
__global__ void k_head(const float* __restrict__ Wlin, const float* __restrict__ blin,
                       float* __restrict__ out)
{
    const int gph = threadIdx.x;
    if (gph >= NG) return;
    const int cnt = g_gstart[gph + 1] - g_gstart[gph];
    const float inv = 1.f / fmaxf((float)cnt, 1.f);
    float l0 = blin[0], l1 = blin[1];
#pragma unroll
    for (int c = 0; c < DH; c++) {
        const float p = g_sums[gph * DH + c] * inv;
        l0 += p * Wlin[c * 2 + 0];
        l1 += p * Wlin[c * 2 + 1];
    }
    const float m   = fmaxf(l0, l1);
    const float lse = m + logf(expf(l0 - m) + expf(l1 - m));
    out[gph * 2 + 0] = l0 - lse;
    out[gph * 2 + 1] = l1 - lse;
}

// ---------------------------------------------------------------------------
extern "C" void kernel_launch(void* const* d_in, const int* in_sizes, int n_in,
                              void* d_out, int out_size)
{
    const void *p_x = 0, *p_ei = 0, *p_batch = 0;
    const void *p_W1[2] = {0, 0};
    const void *p_W23[4] = {0, 0, 0, 0};
    const void *p_b[3] = {0, 0, 0};
    const void *p_Wlin = 0, *p_blin = 0;
    int n64 = 0, n1024 = 0, n32 = 0;
    for (int i = 0; i < n_in; i++) {
        const int s = in_sizes[i];
        if      (s == NN * DIN) p_x = d_in[i];
        else if (s == 2 * NE)   p_ei = d_in[i];
        else if (s == NN)       p_batch = d_in[i];
        else if (s == DIN * DH) { if (n64 < 2) p_W1[n64++] = d_in[i]; }
        else if (s == DH * DH)  { if (n1024 < 4) p_W23[n1024++] = d_in[i]; }
        else if (s == DH)       { if (n32 < 3) p_b[n32++] = d_in[i]; }
        else if (s == DH * 2)   p_Wlin = d_in[i];
        else if (s == 2)        p_blin = d_in[i];
    }
    const float* x    = (const float*)p_x;
    const float* W1r  = (const float*)p_W1[0];
    const float* W1l  = (const float*)p_W1[1];
    const float* b1   = (const float*)p_b[0];
    const float* W2r  = (const float*)p_W23[0];
    const float* W2l  = (const float*)p_W23[1];
    const float* b2   = (const float*)p_b[1];
    const float* W3r  = (const float*)p_W23[2];
    const float* W3l  = (const float*)p_W23[3];
    const float* b3   = (const float*)p_b[2];
    const float* Wlin = (const float*)p_Wlin;
    const float* blin = (const float*)p_blin;
    float* out = (float*)d_out;

    const int FBLKS = (NN + 7) / 8;               // 6250 (warp per node)

    k_detect_zero<<<NBLK, 256>>>((const unsigned*)p_ei, (const unsigned*)p_batch);
    k_conv_hist<<<EBLK, 256>>>(p_ei);
    k_scan_bounds<<<NBLK, 256>>>(p_batch);
    k_gemm1_scatter<<<GBLK + SCB2, 128>>>(x, W1r, W1l, b1);
    k_flayer<<<FBLKS, 256>>>(0, W2r, W2l, b2);    // a -> b (L1 act + L2 linear)
    k_flayer<<<FBLKS, 256>>>(1, W3r, W3l, b3);    // b -> a (L2 act + L3 linear)
    k_flayer3_pool<<<FBLKS, 256>>>(p_batch);      // L3 act + pool
    k_head<<<1, 64>>>(Wlin, blin, out);
}

// round 14
// speedup vs baseline: 2.3621x; 1.5255x over previous
#include <cuda_runtime.h>
#include <math.h>

#define NN 50000
#define NE 400000
#define NG 64
#define DIN 200
#define DH 32
#define NBLK 196    // ceil(NN/256)
#define EBLK2 782   // ceil(NE/512)  (hist: 256 thr x 2 edges)
#define GBLK 391    // ceil(NN/128)  (GEMM blocks: 128 thr, 128 nodes, 64 cols)
#define SCB 1563    // ceil(NE/256)  (scatter blocks: 128 thr x 2 edges)

// ---------------- scratch (device globals — no allocation allowed) ----------
// NOTE: never pass these as kernel args from host code (host shadow symbol +
// ATS silently reads zeros). Select ping-pong buffers with an int in device
// code. ALL scratch explicitly zeroed at the top of every launch — replays
// identical by construction. NO __threadfence (per-block CCTL.IVALL = L1D
// flush; measured disaster). NO node-pair GEMM packing (measured 2.3x
// regression: conflicted LDS.64 W stream).
__device__ __align__(16) float g_tr_a[NN * DH];
__device__ __align__(16) float g_tr_b[NN * DH];
__device__ __align__(16) float g_root_a[NN * DH];
__device__ __align__(16) float g_root_b[NN * DH];
__device__ float g_sums[NG * DH];

__device__ int g_flag_ei;    // nonzero -> edge_index is int32
__device__ int g_flag_b;     // nonzero -> batch is int32

__device__ int g_cnt[NN];
__device__ int g_off[NN];
__device__ int g_cur[NN];
__device__ int g_total;
__device__ int g_esrc[NE];
__device__ int g_gstart[NG + 1];

__device__ __forceinline__ float elu1(float v) { return v > 0.f ? v : expm1f(v); }

#define FMA_X2(acc, a, b) \
    asm("fma.rn.f32x2 %0, %1, %2, %0;" : "+l"(acc) : "l"(a), "l"(b))
#define DUP_X2(out, x) \
    asm("mov.b64 %0, {%1, %1};" : "=l"(out) : "r"(__float_as_uint(x)))
#define UNPK_X2(lo, hi, in) \
    asm("mov.b64 {%0, %1}, %2;" : "=f"(lo), "=f"(hi) : "l"(in))
#define PACK_X2(out, lo, hi) \
    asm("mov.b64 %0, {%1, %2};" : "=l"(out) : "f"(lo), "f"(hi))

// ---------------------------------------------------------------------------
// dtype decode helpers (clamped)
// ---------------------------------------------------------------------------
__device__ __forceinline__ int edge_at(const void* ei_raw, int idx, int is32)
{
    int v = is32 ? ((const int*)ei_raw)[idx] : (int)((const long long*)ei_raw)[idx];
    v &= 0x7fffffff;
    return (v < NN) ? v : 0;
}

__device__ __forceinline__ int batch_at(const void* b_raw, int i, int is32)
{
    int g = is32 ? ((const int*)b_raw)[i] : (int)((const long long*)b_raw)[i];
    g &= 0x7fffffff;
    return (g < NG) ? g : (NG - 1);
}

// ---------------------------------------------------------------------------
// Kernel 1: zero scratch + dtype detection (block 0 samples odd 32-bit words:
// int64 values < 2^31 have zero high words; int32 payloads essentially never do)
// ---------------------------------------------------------------------------
__global__ void k_detect_zero(const unsigned* __restrict__ ei_w,
                              const unsigned* __restrict__ b_w)
{
    const int i = blockIdx.x * blockDim.x + threadIdx.x;
    if (i < NN) g_cnt[i] = 0;
    if (i < NG * DH) g_sums[i] = 0.f;
    if (i == 0) g_total = 0;

    if (blockIdx.x == 0) {
        __shared__ int s_ei, s_b;
        const int tid = threadIdx.x;
        if (tid == 0) { s_ei = 0; s_b = 0; }
        __syncthreads();
        { const int k = tid * 1562;  if (ei_w[2 * k + 1] != 0) atomicOr(&s_ei, 1); }
        { const int k = 24744 + tid; if (b_w[2 * k + 1] != 0)  atomicOr(&s_b, 1); }
        __syncthreads();
        if (tid == 0) { g_flag_ei = s_ei; g_flag_b = s_b; }
    }
}

// ---------------------------------------------------------------------------
// Kernel 2: dst histogram (decodes only dst half of raw edge_index)
// ---------------------------------------------------------------------------
__global__ void k_hist(const void* __restrict__ ei_raw)
{
    const int tid = blockIdx.x * 256 + threadIdx.x;
    const int is32 = g_flag_ei;
#pragma unroll
    for (int q = 0; q < 2; q++) {
        const int e = tid + q * (EBLK2 * 256);
        if (e < NE) atomicAdd(&g_cnt[edge_at(ei_raw, NE + e, is32)], 1);
    }
}

// ---------------------------------------------------------------------------
// Kernel 3: single-pass scan (block scan + atomic base; bases need not be
// monotone since consumers use beg + cnt) fused with graph-boundary build.
// ---------------------------------------------------------------------------
__global__ void k_scan_bounds(const void* __restrict__ b_raw)
{
    __shared__ int s[256];
    __shared__ int base_sh;
    const int tid = threadIdx.x;
    const int i = blockIdx.x * 256 + tid;
    const int v = (i < NN) ? g_cnt[i] : 0;
    s[tid] = v;
    __syncthreads();
#pragma unroll
    for (int d = 1; d < 256; d <<= 1) {
        const int t = (tid >= d) ? s[tid - d] : 0;
        __syncthreads();
        s[tid] += t;
        __syncthreads();
    }
    if (tid == 255) base_sh = atomicAdd(&g_total, s[255]);
    __syncthreads();
    if (i < NN) {
        const int o = base_sh + s[tid] - v;
        g_off[i] = o;
        g_cur[i] = o;
    }

    if (i < NN) {
        const int is32 = g_flag_b;
        const int g  = batch_at(b_raw, i, is32);
        const int gp = (i == 0) ? -1 : batch_at(b_raw, i - 1, is32);
        for (int q = gp + 1; q <= g; q++) g_gstart[q] = i;
        if (i == NN - 1)
            for (int q = g + 1; q <= NG; q++) g_gstart[q] = NN;
    }
}

// ---------------------------------------------------------------------------
// Kernel 4 (fused): blocks [0,GBLK) = GEMM1 (champion 8x8 tile); blocks
// [GBLK,GBLK+SCB) = CSR scatter (decodes raw edges directly).
// GEMM1: [50000,200] @ [W1r|W1l][200,64], packed f32x2, double-buffered smem,
// 128 threads / 128 nodes / 64 cols, one __syncthreads per K-tile.
// ---------------------------------------------------------------------------
__global__ __launch_bounds__(128) void k_gemm1_scatter(const float* __restrict__ x,
                                                       const float* __restrict__ Wr,
                                                       const float* __restrict__ Wl,
                                                       const float* __restrict__ b,
                                                       const void* __restrict__ ei_raw)
{
    if (blockIdx.x >= GBLK) {
        const int base = (blockIdx.x - GBLK) * 256 + threadIdx.x;
        const int is32 = g_flag_ei;
#pragma unroll
        for (int q = 0; q < 2; q++) {
            const int e = base + q * 128;
            if (e < NE) {
                const int d = edge_at(ei_raw, NE + e, is32);
                const int s = edge_at(ei_raw, e, is32);
                const int pos = atomicAdd(&g_cur[d], 1);
                g_esrc[pos] = s;
            }
        }
        return;
    }

    __shared__ __align__(16) float Xs[2][8 * 128];   // [buf][k][node]
    __shared__ __align__(16) float Wsc[2][8 * 64];   // [buf][k*64+c]
    __shared__ float bs[32];

    const int tid = threadIdx.x;
    const int n0  = blockIdx.x * 128;
    if (tid < 32) bs[tid] = b[tid];

    const int cg = tid & 7;        // col group (8 cols = 4 packed pairs)
    const int ng = tid >> 3;       // node group (8 nodes), 0..15

    unsigned long long acc2[8][4];
#pragma unroll
    for (int i = 0; i < 8; i++)
#pragma unroll
        for (int j = 0; j < 4; j++) acc2[i][j] = 0ULL;

    const int  nld = n0 + tid;
    const bool vld = nld < NN;
    const float4* xrow = reinterpret_cast<const float4*>(x + (long)nld * DIN);

    float4 xa, xb;
    float  wv[4];

#define LOAD_TILE(t)                                                          \
    do {                                                                      \
        xa = make_float4(0.f, 0.f, 0.f, 0.f); xb = xa;                        \
        if (vld) { xa = xrow[(t) * 2]; xb = xrow[(t) * 2 + 1]; }              \
        _Pragma("unroll")                                                     \
        for (int j = 0; j < 4; j++) {                                         \
            const int idx = j * 128 + tid;       /* 0..511 = k*64+c */        \
            const int kk = idx >> 6, c = idx & 63;                            \
            wv[j] = (c < 32) ? Wr[((t) * 8 + kk) * 32 + c]                    \
                             : Wl[((t) * 8 + kk) * 32 + c - 32];              \
        }                                                                     \
    } while (0)

#define STORE_TILE(bf)                                                        \
    do {                                                                      \
        Xs[bf][0 * 128 + tid] = xa.x; Xs[bf][1 * 128 + tid] = xa.y;           \
        Xs[bf][2 * 128 + tid] = xa.z; Xs[bf][3 * 128 + tid] = xa.w;           \
        Xs[bf][4 * 128 + tid] = xb.x; Xs[bf][5 * 128 + tid] = xb.y;           \
        Xs[bf][6 * 128 + tid] = xb.z; Xs[bf][7 * 128 + tid] = xb.w;           \
        _Pragma("unroll")                                                     \
        for (int j = 0; j < 4; j++) Wsc[bf][j * 128 + tid] = wv[j];           \
    } while (0)

    LOAD_TILE(0);
    STORE_TILE(0);
    __syncthreads();

    int buf = 0;
    for (int t = 0; t < 25; t++) {
        if (t < 24) LOAD_TILE(t + 1);                // LDG in flight during compute

#pragma unroll
        for (int kk = 0; kk < 8; kk++) {
            const float4* xp = reinterpret_cast<const float4*>(Xs[buf] + kk * 128 + ng * 8);
            const float4 a0 = xp[0], a1 = xp[1];
            const unsigned long long* wp =
                reinterpret_cast<const unsigned long long*>(Wsc[buf] + kk * 64 + cg * 8);
            const unsigned long long w0 = wp[0], w1p = wp[1], w2p = wp[2], w3p = wp[3];
            const float xv[8] = {a0.x, a0.y, a0.z, a0.w, a1.x, a1.y, a1.z, a1.w};
#pragma unroll
            for (int i = 0; i < 8; i++) {
                unsigned long long xd;
                DUP_X2(xd, xv[i]);
                FMA_X2(acc2[i][0], xd, w0);
                FMA_X2(acc2[i][1], xd, w1p);
                FMA_X2(acc2[i][2], xd, w2p);
                FMA_X2(acc2[i][3], xd, w3p);
            }
        }

        if (t < 24) STORE_TILE(buf ^ 1);             // other buffer: race-free
        __syncthreads();
        buf ^= 1;
    }
#undef LOAD_TILE
#undef STORE_TILE

    const int c0 = cg * 8;
#pragma unroll
    for (int i = 0; i < 8; i++) {
        const int node = n0 + ng * 8 + i;
        if (node >= NN) continue;
        float c[8];
#pragma unroll
        for (int j = 0; j < 4; j++) UNPK_X2(c[2 * j], c[2 * j + 1], acc2[i][j]);
        float4 lo = make_float4(c[0], c[1], c[2], c[3]);
        float4 hi = make_float4(c[4], c[5], c[6], c[7]);
        if (cg < 4) {
            *reinterpret_cast<float4*>(g_tr_a + node * DH + c0)     = lo;
            *reinterpret_cast<float4*>(g_tr_a + node * DH + c0 + 4) = hi;
        } else {
            const int cc = c0 - 32;
            lo.x += bs[cc + 0]; lo.y += bs[cc + 1]; lo.z += bs[cc + 2]; lo.w += bs[cc + 3];
            hi.x += bs[cc + 4]; hi.y += bs[cc + 5]; hi.z += bs[cc + 6]; hi.w += bs[cc + 7];
            *reinterpret_cast<float4*>(g_root_a + node * DH + cc)     = lo;
            *reinterpret_cast<float4*>(g_root_a + node * DH + cc + 4) = hi;
        }
    }
}

// ---------------------------------------------------------------------------
// Fused layer kernel (layers 1->2, 2->3): warp per node; buffers picked by sel
// in device code (sel=0: a->b, sel=1: b->a). Gather unrolled x8 (MLP 8).
// ---------------------------------------------------------------------------
__global__ __launch_bounds__(256) void k_flayer(int sel,
                                                const float* __restrict__ Wr,
                                                const float* __restrict__ Wl,
                                                const float* __restrict__ b)
{
    __shared__ __align__(16) unsigned long long Wp[32 * 32];  // [k][lane]=(Wr,Wl)
    __shared__ float bs[32];
    __shared__ float hs[8][32];

    const int tid = threadIdx.x;
    for (int i = tid; i < 1024; i += 256) {
        const int k = i >> 5, c = i & 31;
        unsigned long long p;
        PACK_X2(p, Wr[k * 32 + c], Wl[k * 32 + c]);
        Wp[i] = p;
    }
    if (tid < 32) bs[tid] = b[tid];
    __syncthreads();

    const float* tr_in   = sel ? g_tr_b   : g_tr_a;
    const float* root_in = sel ? g_root_b : g_root_a;
    float* tr_out   = sel ? g_tr_a   : g_tr_b;
    float* root_out = sel ? g_root_a : g_root_b;

    const int w    = tid >> 5;
    const int lane = tid & 31;
    const int node = (blockIdx.x << 3) + w;
    if (node >= NN) return;

    const int beg = g_off[node];
    const int end = beg + g_cnt[node];
    float acc = 0.f;
    int k = beg;
    for (; k + 7 < end; k += 8) {                 // MLP=8 over L2-latency gathers
        const int s0 = g_esrc[k + 0], s1 = g_esrc[k + 1];
        const int s2 = g_esrc[k + 2], s3 = g_esrc[k + 3];
        const int s4 = g_esrc[k + 4], s5 = g_esrc[k + 5];
        const int s6 = g_esrc[k + 6], s7 = g_esrc[k + 7];
        const float v0 = tr_in[s0 * DH + lane], v1 = tr_in[s1 * DH + lane];
        const float v2 = tr_in[s2 * DH + lane], v3 = tr_in[s3 * DH + lane];
        const float v4 = tr_in[s4 * DH + lane], v5 = tr_in[s5 * DH + lane];
        const float v6 = tr_in[s6 * DH + lane], v7 = tr_in[s7 * DH + lane];
        acc += ((v0 + v1) + (v2 + v3)) + ((v4 + v5) + (v6 + v7));
    }
    for (; k < end; k++) acc += tr_in[g_esrc[k] * DH + lane];

    const float h = elu1(acc + root_in[node * DH + lane]);
    hs[w][lane] = h;
    __syncwarp();

    unsigned long long a2 = 0ULL;
#pragma unroll
    for (int kk = 0; kk < 32; kk++) {
        unsigned long long hd;
        DUP_X2(hd, hs[w][kk]);                    // LDS broadcast
        FMA_X2(a2, hd, Wp[kk * 32 + lane]);
    }
    float m, r;
    UNPK_X2(m, r, a2);
    tr_out[node * DH + lane]   = m;
    root_out[node * DH + lane] = r + bs[lane];
}

// ---------------------------------------------------------------------------
// Fused layer 3 + pool: reads a-buffers; h = elu(aggr + root); atomic pool.
// Gather unrolled x8 (MLP 8).
// ---------------------------------------------------------------------------
__global__ __launch_bounds__(256) void k_flayer3_pool(const void* __restrict__ b_raw)
{
    const int tid  = threadIdx.x;
    const int w    = tid >> 5;
    const int lane = tid & 31;
    const int node = (blockIdx.x << 3) + w;
    if (node >= NN) return;

    const int beg = g_off[node];
    const int end = beg + g_cnt[node];
    float acc = 0.f;
    int k = beg;
    for (; k + 7 < end; k += 8) {
        const int s0 = g_esrc[k + 0], s1 = g_esrc[k + 1];
        const int s2 = g_esrc[k + 2], s3 = g_esrc[k + 3];
        const int s4 = g_esrc[k + 4], s5 = g_esrc[k + 5];
        const int s6 = g_esrc[k + 6], s7 = g_esrc[k + 7];
        const float v0 = g_tr_a[s0 * DH + lane], v1 = g_tr_a[s1 * DH + lane];
        const float v2 = g_tr_a[s2 * DH + lane], v3 = g_tr_a[s3 * DH + lane];
        const float v4 = g_tr_a[s4 * DH + lane], v5 = g_tr_a[s5 * DH + lane];
        const float v6 = g_tr_a[s6 * DH + lane], v7 = g_tr_a[s7 * DH + lane];
        acc += ((v0 + v1) + (v2 + v3)) + ((v4 + v5) + (v6 + v7));
    }
    for (; k < end; k++) acc += g_tr_a[g_esrc[k] * DH + lane];

    const float h = elu1(acc + g_root_a[node * DH + lane]);
    const int g = batch_at(b_raw, node, g_flag_b);
    atomicAdd(&g_sums[g * DH + lane], h);
}

// ---------------------------------------------------------------------------
// Head: pooled mean -> linear[32,2] -> log_softmax
// ---------------------------------------------------------------------------
__global__ void k_head(const float* __restrict__ Wlin, const float* __restrict__ blin,
                       float* __restrict__ out)
{
    const int gph = threadIdx.x;
    if (gph >= NG) return;
    const int cnt = g_gstart[gph + 1] - g_gstart[gph];
    const float inv = 1.f / fmaxf((float)cnt, 1.f);
    float l0 = blin[0], l1 = blin[1];
#pragma unroll
    for (int c = 0; c < DH; c++) {
        const float p = g_sums[gph * DH + c] * inv;
        l0 += p * Wlin[c * 2 + 0];
        l1 += p * Wlin[c * 2 + 1];
    }
    const float m   = fmaxf(l0, l1);
    const float lse = m + logf(expf(l0 - m) + expf(l1 - m));
    out[gph * 2 + 0] = l0 - lse;
    out[gph * 2 + 1] = l1 - lse;
}

// ---------------------------------------------------------------------------
extern "C" void kernel_launch(void* const* d_in, const int* in_sizes, int n_in,
                              void* d_out, int out_size)
{
    const void *p_x = 0, *p_ei = 0, *p_batch = 0;
    const void *p_W1[2] = {0, 0};
    const void *p_W23[4] = {0, 0, 0, 0};
    const void *p_b[3] = {0, 0, 0};
    const void *p_Wlin = 0, *p_blin = 0;
    int n64 = 0, n1024 = 0, n32 = 0;
    for (int i = 0; i < n_in; i++) {
        const int s = in_sizes[i];
        if      (s == NN * DIN) p_x = d_in[i];
        else if (s == 2 * NE)   p_ei = d_in[i];
        else if (s == NN)       p_batch = d_in[i];
        else if (s == DIN * DH) { if (n64 < 2) p_W1[n64++] = d_in[i]; }
        else if (s == DH * DH)  { if (n1024 < 4) p_W23[n1024++] = d_in[i]; }
        else if (s == DH)       { if (n32 < 3) p_b[n32++] = d_in[i]; }
        else if (s == DH * 2)   p_Wlin = d_in[i];
        else if (s == 2)        p_blin = d_in[i];
    }
    const float* x    = (const float*)p_x;
    const float* W1r  = (const float*)p_W1[0];
    const float* W1l  = (const float*)p_W1[1];
    const float* b1   = (const float*)p_b[0];
    const float* W2r  = (const float*)p_W23[0];
    const float* W2l  = (const float*)p_W23[1];
    const float* b2   = (const float*)p_b[1];
    const float* W3r  = (const float*)p_W23[2];
    const float* W3l  = (const float*)p_W23[3];
    const float* b3   = (const float*)p_b[2];
    const float* Wlin = (const float*)p_Wlin;
    const float* blin = (const float*)p_blin;
    float* out = (float*)d_out;

    const int FBLKS = (NN + 7) / 8;               // 6250 (warp per node)

    k_detect_zero<<<NBLK, 256>>>((const unsigned*)p_ei, (const unsigned*)p_batch);
    k_hist<<<EBLK2, 256>>>(p_ei);
    k_scan_bounds<<<NBLK, 256>>>(p_batch);
    k_gemm1_scatter<<<GBLK + SCB, 128>>>(x, W1r, W1l, b1, p_ei);
    k_flayer<<<FBLKS, 256>>>(0, W2r, W2l, b2);    // a -> b (L1 act + L2 linear)
    k_flayer<<<FBLKS, 256>>>(1, W3r, W3l, b3);    // b -> a (L2 act + L3 linear)
    k_flayer3_pool<<<FBLKS, 256>>>(p_batch);      // L3 act + pool
    k_head<<<1, 64>>>(Wlin, blin, out);
}

// round 15
// speedup vs baseline: 2.5955x; 1.0988x over previous
#include <cuda_runtime.h>
#include <math.h>

#define NN 50000
#define NE 400000
#define NG 64
#define DIN 200
#define DH 32
#define NBLK 196    // ceil(NN/256)
#define EBLK2 782   // ceil(NE/512)  (hist: 256 thr x 2 edges)
#define GBLK 391    // ceil(NN/128)  (GEMM blocks: 256 thr, 128 nodes, 64 cols)
#define SCB 782     // ceil(NE/512)  (scatter blocks: 256 thr x 2 edges)

// ---------------- scratch (device globals — no allocation allowed) ----------
// NOTE: never pass these as kernel args from host code (host shadow symbol +
// ATS silently reads zeros). Select ping-pong buffers with an int in device
// code. ALL scratch explicitly zeroed at the top of every launch — replays
// identical by construction. NO __threadfence (per-block CCTL.IVALL = L1D
// flush; measured disaster). NO pre-duplicated-W-in-smem (measured 2.3x
// regression: conflicted LDS.64 stream). Micro-tile must keep smem bytes per
// FMA2 <= ~10 (crossbar 128 B/cyc/SM; round 9's 20 B/FMA2 tile regressed).
__device__ __align__(16) float g_tr_a[NN * DH];
__device__ __align__(16) float g_tr_b[NN * DH];
__device__ __align__(16) float g_root_a[NN * DH];
__device__ __align__(16) float g_root_b[NN * DH];
__device__ float g_sums[NG * DH];

__device__ int g_flag_ei;    // nonzero -> edge_index is int32
__device__ int g_flag_b;     // nonzero -> batch is int32

__device__ int g_cnt[NN];
__device__ int g_off[NN];
__device__ int g_cur[NN];
__device__ int g_total;
__device__ int g_esrc[NE];
__device__ int g_gstart[NG + 1];

__device__ __forceinline__ float elu1(float v) { return v > 0.f ? v : expm1f(v); }

#define FMA_X2(acc, a, b) \
    asm("fma.rn.f32x2 %0, %1, %2, %0;" : "+l"(acc) : "l"(a), "l"(b))
#define DUP_X2(out, x) \
    asm("mov.b64 %0, {%1, %1};" : "=l"(out) : "r"(__float_as_uint(x)))
#define UNPK_X2(lo, hi, in) \
    asm("mov.b64 {%0, %1}, %2;" : "=f"(lo), "=f"(hi) : "l"(in))
#define PACK_X2(out, lo, hi) \
    asm("mov.b64 %0, {%1, %2};" : "=l"(out) : "f"(lo), "f"(hi))

// ---------------------------------------------------------------------------
// dtype decode helpers (clamped)
// ---------------------------------------------------------------------------
__device__ __forceinline__ int edge_at(const void* ei_raw, int idx, int is32)
{
    int v = is32 ? ((const int*)ei_raw)[idx] : (int)((const long long*)ei_raw)[idx];
    v &= 0x7fffffff;
    return (v < NN) ? v : 0;
}

__device__ __forceinline__ int batch_at(const void* b_raw, int i, int is32)
{
    int g = is32 ? ((const int*)b_raw)[i] : (int)((const long long*)b_raw)[i];
    g &= 0x7fffffff;
    return (g < NG) ? g : (NG - 1);
}

// ---------------------------------------------------------------------------
// Kernel 1: zero scratch + dtype detection (block 0 samples odd 32-bit words:
// int64 values < 2^31 have zero high words; int32 payloads essentially never do)
// ---------------------------------------------------------------------------
__global__ void k_detect_zero(const unsigned* __restrict__ ei_w,
                              const unsigned* __restrict__ b_w)
{
    const int i = blockIdx.x * blockDim.x + threadIdx.x;
    if (i < NN) g_cnt[i] = 0;
    if (i < NG * DH) g_sums[i] = 0.f;
    if (i == 0) g_total = 0;

    if (blockIdx.x == 0) {
        __shared__ int s_ei, s_b;
        const int tid = threadIdx.x;
        if (tid == 0) { s_ei = 0; s_b = 0; }
        __syncthreads();
        { const int k = tid * 1562;  if (ei_w[2 * k + 1] != 0) atomicOr(&s_ei, 1); }
        { const int k = 24744 + tid; if (b_w[2 * k + 1] != 0)  atomicOr(&s_b, 1); }
        __syncthreads();
        if (tid == 0) { g_flag_ei = s_ei; g_flag_b = s_b; }
    }
}

// ---------------------------------------------------------------------------
// Kernel 2: dst histogram (decodes only dst half of raw edge_index)
// ---------------------------------------------------------------------------
__global__ void k_hist(const void* __restrict__ ei_raw)
{
    const int tid = blockIdx.x * 256 + threadIdx.x;
    const int is32 = g_flag_ei;
#pragma unroll
    for (int q = 0; q < 2; q++) {
        const int e = tid + q * (EBLK2 * 256);
        if (e < NE) atomicAdd(&g_cnt[edge_at(ei_raw, NE + e, is32)], 1);
    }
}

// ---------------------------------------------------------------------------
// Kernel 3: single-pass scan (block scan + atomic base; bases need not be
// monotone since consumers use beg + cnt) fused with graph-boundary build.
// ---------------------------------------------------------------------------
__global__ void k_scan_bounds(const void* __restrict__ b_raw)
{
    __shared__ int s[256];
    __shared__ int base_sh;
    const int tid = threadIdx.x;
    const int i = blockIdx.x * 256 + tid;
    const int v = (i < NN) ? g_cnt[i] : 0;
    s[tid] = v;
    __syncthreads();
#pragma unroll
    for (int d = 1; d < 256; d <<= 1) {
        const int t = (tid >= d) ? s[tid - d] : 0;
        __syncthreads();
        s[tid] += t;
        __syncthreads();
    }
    if (tid == 255) base_sh = atomicAdd(&g_total, s[255]);
    __syncthreads();
    if (i < NN) {
        const int o = base_sh + s[tid] - v;
        g_off[i] = o;
        g_cur[i] = o;
    }

    if (i < NN) {
        const int is32 = g_flag_b;
        const int g  = batch_at(b_raw, i, is32);
        const int gp = (i == 0) ? -1 : batch_at(b_raw, i - 1, is32);
        for (int q = gp + 1; q <= g; q++) g_gstart[q] = i;
        if (i == NN - 1)
            for (int q = g + 1; q <= NG; q++) g_gstart[q] = NN;
    }
}

// ---------------------------------------------------------------------------
// Kernel 4 (fused): blocks [0,GBLK) = GEMM1; blocks [GBLK,GBLK+SCB) = CSR
// scatter (decodes raw edges directly).
// GEMM1: [50000,200] @ [W1r|W1l][200,64], packed f32x2, double-buffered smem.
// 256 threads / 128 nodes / 64 cols; 8 nodes x 4 cols per thread (10 B smem
// per FMA2 -> crossbar-safe); ~70 regs -> 4 CTAs/SM = 32 warps (latency
// hidden by warp parallelism). tid<128 stages X; all 256 stage W.
// ---------------------------------------------------------------------------
__global__ __launch_bounds__(256) void k_gemm1_scatter(const float* __restrict__ x,
                                                       const float* __restrict__ Wr,
                                                       const float* __restrict__ Wl,
                                                       const float* __restrict__ b,
                                                       const void* __restrict__ ei_raw)
{
    if (blockIdx.x >= GBLK) {
        const int base = (blockIdx.x - GBLK) * 512 + threadIdx.x;
        const int is32 = g_flag_ei;
#pragma unroll
        for (int q = 0; q < 2; q++) {
            const int e = base + q * 256;
            if (e < NE) {
                const int d = edge_at(ei_raw, NE + e, is32);
                const int s = edge_at(ei_raw, e, is32);
                const int pos = atomicAdd(&g_cur[d], 1);
                g_esrc[pos] = s;
            }
        }
        return;
    }

    __shared__ __align__(16) float Xs[2][8 * 128];   // [buf][k][node]
    __shared__ __align__(16) float Wsc[2][8 * 64];   // [buf][k*64+c]
    __shared__ float bs[32];

    const int tid = threadIdx.x;
    const int n0  = blockIdx.x * 128;
    if (tid < 32) bs[tid] = b[tid];

    const int cg = tid & 15;       // col group (4 cols), 0..15
    const int ng = tid >> 4;       // node group (8 nodes), 0..15

    unsigned long long acc2[8][2]; // [node][col pair]
#pragma unroll
    for (int i = 0; i < 8; i++) { acc2[i][0] = 0ULL; acc2[i][1] = 0ULL; }

    const bool is_x = tid < 128;
    const int  nld = n0 + tid;
    const bool vld = is_x && (nld < NN);
    const float4* xrow = reinterpret_cast<const float4*>(x + (long)nld * DIN);

    float4 xa, xb;
    float  wv[2];

#define LOAD_TILE(t)                                                          \
    do {                                                                      \
        if (is_x) {                                                           \
            xa = make_float4(0.f, 0.f, 0.f, 0.f); xb = xa;                    \
            if (vld) { xa = xrow[(t) * 2]; xb = xrow[(t) * 2 + 1]; }          \
        }                                                                     \
        _Pragma("unroll")                                                     \
        for (int j = 0; j < 2; j++) {                                         \
            const int idx = j * 256 + tid;       /* 0..511 = kk*64+c */       \
            const int kk = idx >> 6, c = idx & 63;                            \
            wv[j] = (c < 32) ? Wr[((t) * 8 + kk) * 32 + c]                    \
                             : Wl[((t) * 8 + kk) * 32 + c - 32];              \
        }                                                                     \
    } while (0)

#define STORE_TILE(bf)                                                        \
    do {                                                                      \
        if (is_x) {                                                           \
            Xs[bf][0 * 128 + tid] = xa.x; Xs[bf][1 * 128 + tid] = xa.y;       \
            Xs[bf][2 * 128 + tid] = xa.z; Xs[bf][3 * 128 + tid] = xa.w;       \
            Xs[bf][4 * 128 + tid] = xb.x; Xs[bf][5 * 128 + tid] = xb.y;       \
            Xs[bf][6 * 128 + tid] = xb.z; Xs[bf][7 * 128 + tid] = xb.w;       \
        }                                                                     \
        _Pragma("unroll")                                                     \
        for (int j = 0; j < 2; j++) Wsc[bf][j * 256 + tid] = wv[j];           \
    } while (0)

    LOAD_TILE(0);
    STORE_TILE(0);
    __syncthreads();

    int buf = 0;
    for (int t = 0; t < 25; t++) {
        if (t < 24) LOAD_TILE(t + 1);                // LDG in flight during compute

#pragma unroll
        for (int kk = 0; kk < 8; kk++) {
            const float4* xp = reinterpret_cast<const float4*>(Xs[buf] + kk * 128 + ng * 8);
            const float4 a0 = xp[0], a1 = xp[1];
            const unsigned long long* wp =
                reinterpret_cast<const unsigned long long*>(Wsc[buf] + kk * 64 + cg * 4);
            const unsigned long long w0 = wp[0], w1p = wp[1];
            const float xv[8] = {a0.x, a0.y, a0.z, a0.w, a1.x, a1.y, a1.z, a1.w};
#pragma unroll
            for (int i = 0; i < 8; i++) {
                unsigned long long xd;
                DUP_X2(xd, xv[i]);
                FMA_X2(acc2[i][0], xd, w0);
                FMA_X2(acc2[i][1], xd, w1p);
            }
        }

        if (t < 24) STORE_TILE(buf ^ 1);             // other buffer: race-free
        __syncthreads();
        buf ^= 1;
    }
#undef LOAD_TILE
#undef STORE_TILE

    const int c0 = cg * 4;
#pragma unroll
    for (int i = 0; i < 8; i++) {
        const int node = n0 + ng * 8 + i;
        if (node >= NN) continue;
        float c[4];
        UNPK_X2(c[0], c[1], acc2[i][0]);
        UNPK_X2(c[2], c[3], acc2[i][1]);
        float4 v = make_float4(c[0], c[1], c[2], c[3]);
        if (cg < 8) {
            *reinterpret_cast<float4*>(g_tr_a + node * DH + c0) = v;
        } else {
            const int cc = c0 - 32;
            v.x += bs[cc + 0]; v.y += bs[cc + 1]; v.z += bs[cc + 2]; v.w += bs[cc + 3];
            *reinterpret_cast<float4*>(g_root_a + node * DH + cc) = v;
        }
    }
}

// ---------------------------------------------------------------------------
// Fused layer kernel (layers 1->2, 2->3): warp per node; buffers picked by sel
// in device code (sel=0: a->b, sel=1: b->a). Gather unrolled x8 (MLP 8).
// ---------------------------------------------------------------------------
__global__ __launch_bounds__(256) void k_flayer(int sel,
                                                const float* __restrict__ Wr,
                                                const float* __restrict__ Wl,
                                                const float* __restrict__ b)
{
    __shared__ __align__(16) unsigned long long Wp[32 * 32];  // [k][lane]=(Wr,Wl)
    __shared__ float bs[32];
    __shared__ float hs[8][32];

    const int tid = threadIdx.x;
    for (int i = tid; i < 1024; i += 256) {
        const int k = i >> 5, c = i & 31;
        unsigned long long p;
        PACK_X2(p, Wr[k * 32 + c], Wl[k * 32 + c]);
        Wp[i] = p;
    }
    if (tid < 32) bs[tid] = b[tid];
    __syncthreads();

    const float* tr_in   = sel ? g_tr_b   : g_tr_a;
    const float* root_in = sel ? g_root_b : g_root_a;
    float* tr_out   = sel ? g_tr_a   : g_tr_b;
    float* root_out = sel ? g_root_a : g_root_b;

    const int w    = tid >> 5;
    const int lane = tid & 31;
    const int node = (blockIdx.x << 3) + w;
    if (node >= NN) return;

    const int beg = g_off[node];
    const int end = beg + g_cnt[node];
    float acc = 0.f;
    int k = beg;
    for (; k + 7 < end; k += 8) {                 // MLP=8 over L2-latency gathers
        const int s0 = g_esrc[k + 0], s1 = g_esrc[k + 1];
        const int s2 = g_esrc[k + 2], s3 = g_esrc[k + 3];
        const int s4 = g_esrc[k + 4], s5 = g_esrc[k + 5];
        const int s6 = g_esrc[k + 6], s7 = g_esrc[k + 7];
        const float v0 = tr_in[s0 * DH + lane], v1 = tr_in[s1 * DH + lane];
        const float v2 = tr_in[s2 * DH + lane], v3 = tr_in[s3 * DH + lane];
        const float v4 = tr_in[s4 * DH + lane], v5 = tr_in[s5 * DH + lane];
        const float v6 = tr_in[s6 * DH + lane], v7 = tr_in[s7 * DH + lane];
        acc += ((v0 + v1) + (v2 + v3)) + ((v4 + v5) + (v6 + v7));
    }
    for (; k < end; k++) acc += tr_in[g_esrc[k] * DH + lane];

    const float h = elu1(acc + root_in[node * DH + lane]);
    hs[w][lane] = h;
    __syncwarp();

    unsigned long long a2 = 0ULL;
#pragma unroll
    for (int kk = 0; kk < 32; kk++) {
        unsigned long long hd;
        DUP_X2(hd, hs[w][kk]);                    // LDS broadcast
        FMA_X2(a2, hd, Wp[kk * 32 + lane]);
    }
    float m, r;
    UNPK_X2(m, r, a2);
    tr_out[node * DH + lane]   = m;
    root_out[node * DH + lane] = r + bs[lane];
}

// ---------------------------------------------------------------------------
// Fused layer 3 + pool: reads a-buffers; h = elu(aggr + root); atomic pool.
// Gather unrolled x8 (MLP 8).
// ---------------------------------------------------------------------------
__global__ __launch_bounds__(256) void k_flayer3_pool(const void* __restrict__ b_raw)
{
    const int tid  = threadIdx.x;
    const int w    = tid >> 5;
    const int lane = tid & 31;
    const int node = (blockIdx.x << 3) + w;
    if (node >= NN) return;

    const int beg = g_off[node];
    const int end = beg + g_cnt[node];
    float acc = 0.f;
    int k = beg;
    for (; k + 7 < end; k += 8) {
        const int s0 = g_esrc[k + 0], s1 = g_esrc[k + 1];
        const int s2 = g_esrc[k + 2], s3 = g_esrc[k + 3];
        const int s4 = g_esrc[k + 4], s5 = g_esrc[k + 5];
        const int s6 = g_esrc[k + 6], s7 = g_esrc[k + 7];
        const float v0 = g_tr_a[s0 * DH + lane], v1 = g_tr_a[s1 * DH + lane];
        const float v2 = g_tr_a[s2 * DH + lane], v3 = g_tr_a[s3 * DH + lane];
        const float v4 = g_tr_a[s4 * DH + lane], v5 = g_tr_a[s5 * DH + lane];
        const float v6 = g_tr_a[s6 * DH + lane], v7 = g_tr_a[s7 * DH + lane];
        acc += ((v0 + v1) + (v2 + v3)) + ((v4 + v5) + (v6 + v7));
    }
    for (; k < end; k++) acc += g_tr_a[g_esrc[k] * DH + lane];

    const float h = elu1(acc + g_root_a[node * DH + lane]);
    const int g = batch_at(b_raw, node, g_flag_b);
    atomicAdd(&g_sums[g * DH + lane], h);
}

// ---------------------------------------------------------------------------
// Head: pooled mean -> linear[32,2] -> log_softmax
// ---------------------------------------------------------------------------
__global__ void k_head(const float* __restrict__ Wlin, const float* __restrict__ blin,
                       float* __restrict__ out)
{
    const int gph = threadIdx.x;
    if (gph >= NG) return;
    const int cnt = g_gstart[gph + 1] - g_gstart[gph];
    const float inv = 1.f / fmaxf((float)cnt, 1.f);
    float l0 = blin[0], l1 = blin[1];
#pragma unroll
    for (int c = 0; c < DH; c++) {
        const float p = g_sums[gph * DH + c] * inv;
        l0 += p * Wlin[c * 2 + 0];
        l1 += p * Wlin[c * 2 + 1];
    }
    const float m   = fmaxf(l0, l1);
    const float lse = m + logf(expf(l0 - m) + expf(l1 - m));
    out[gph * 2 + 0] = l0 - lse;
    out[gph * 2 + 1] = l1 - lse;
}

// ---------------------------------------------------------------------------
extern "C" void kernel_launch(void* const* d_in, const int* in_sizes, int n_in,
                              void* d_out, int out_size)
{
    const void *p_x = 0, *p_ei = 0, *p_batch = 0;
    const void *p_W1[2] = {0, 0};
    const void *p_W23[4] = {0, 0, 0, 0};
    const void *p_b[3] = {0, 0, 0};
    const void *p_Wlin = 0, *p_blin = 0;
    int n64 = 0, n1024 = 0, n32 = 0;
    for (int i = 0; i < n_in; i++) {
        const int s = in_sizes[i];
        if      (s == NN * DIN) p_x = d_in[i];
        else if (s == 2 * NE)   p_ei = d_in[i];
        else if (s == NN)       p_batch = d_in[i];
        else if (s == DIN * DH) { if (n64 < 2) p_W1[n64++] = d_in[i]; }
        else if (s == DH * DH)  { if (n1024 < 4) p_W23[n1024++] = d_in[i]; }
        else if (s == DH)       { if (n32 < 3) p_b[n32++] = d_in[i]; }
        else if (s == DH * 2)   p_Wlin = d_in[i];
        else if (s == 2)        p_blin = d_in[i];
    }
    const float* x    = (const float*)p_x;
    const float* W1r  = (const float*)p_W1[0];
    const float* W1l  = (const float*)p_W1[1];
    const float* b1   = (const float*)p_b[0];
    const float* W2r  = (const float*)p_W23[0];
    const float* W2l  = (const float*)p_W23[1];
    const float* b2   = (const float*)p_b[1];
    const float* W3r  = (const float*)p_W23[2];
    const float* W3l  = (const float*)p_W23[3];
    const float* b3   = (const float*)p_b[2];
    const float* Wlin = (const float*)p_Wlin;
    const float* blin = (const float*)p_blin;
    float* out = (float*)d_out;

    const int FBLKS = (NN + 7) / 8;               // 6250 (warp per node)

    k_detect_zero<<<NBLK, 256>>>((const unsigned*)p_ei, (const unsigned*)p_batch);
    k_hist<<<EBLK2, 256>>>(p_ei);
    k_scan_bounds<<<NBLK, 256>>>(p_batch);
    k_gemm1_scatter<<<GBLK + SCB, 256>>>(x, W1r, W1l, b1, p_ei);
    k_flayer<<<FBLKS, 256>>>(0, W2r, W2l, b2);    // a -> b (L1 act + L2 linear)
    k_flayer<<<FBLKS, 256>>>(1, W3r, W3l, b3);    // b -> a (L2 act + L3 linear)
    k_flayer3_pool<<<FBLKS, 256>>>(p_batch);      // L3 act + pool
    k_head<<<1, 64>>>(Wlin, blin, out);
}